// round 4
// baseline (speedup 1.0000x reference)
#include <cuda_runtime.h>
#include <cstdint>
#include <math.h>

#define E_ 8
#define C_ 1024
#define H_ 2048
#define I_ 5632

// inter/gate scratch [E, C, I] fp32 (176 MB)
__device__ float g_scratch[(size_t)E_ * C_ * I_];

constexpr int BM = 128, BN = 128, BK = 32;
constexpr int S = 3;                         // pipeline stages
constexpr int LDSW = 36;                     // padded row stride (floats)
constexpr int STAGE_F = (BM + BN) * LDSW;    // 9216 floats per stage
constexpr int SMEM_BYTES = S * STAGE_F * 4;  // 110592 B -> 2 CTAs/SM
constexpr int THREADS = 256;

__device__ __forceinline__ uint32_t f2tf32(float x) {
    uint32_t y;
    asm("cvt.rna.tf32.f32 %0, %1;" : "=r"(y) : "f"(x));
    return y;
}

__device__ __forceinline__ void mma_tf32(float (&c)[4], const uint32_t (&a)[4],
                                         const uint32_t (&b)[2]) {
    asm volatile(
        "mma.sync.aligned.m16n8k8.row.col.f32.tf32.tf32.f32 "
        "{%0,%1,%2,%3}, {%4,%5,%6,%7}, {%8,%9}, {%0,%1,%2,%3};\n"
        : "+f"(c[0]), "+f"(c[1]), "+f"(c[2]), "+f"(c[3])
        : "r"(a[0]), "r"(a[1]), "r"(a[2]), "r"(a[3]), "r"(b[0]), "r"(b[1]));
}

__device__ __forceinline__ void cp_async16(void* smem_ptr, const void* gmem_ptr) {
    uint32_t s = (uint32_t)__cvta_generic_to_shared(smem_ptr);
    asm volatile("cp.async.cg.shared.global [%0], [%1], 16;\n" ::"r"(s), "l"(gmem_ptr));
}
__device__ __forceinline__ void cp_commit() { asm volatile("cp.async.commit_group;\n"); }
template <int N>
__device__ __forceinline__ void cp_wait() {
    asm volatile("cp.async.wait_group %0;\n" ::"n"(N));
}

// C[e,m,n] = sum_k A[e,m,k] * B[e,n,k]  (NT)
// MODE 0: store raw accumulator              (gate -> scratch)
// MODE 1: out = tf32round(silu(Gpre)*acc)    (up, fused SwiGLU -> scratch in place)
// MODE 2: store raw accumulator              (down -> d_out)
template <int MODE>
__global__ void __launch_bounds__(THREADS)
gemm_nt(const float* __restrict__ A, const float* __restrict__ B,
        const float* __restrict__ Gpre, float* __restrict__ Cout,
        int N, int K, long strideA, long strideB, long strideC) {
    extern __shared__ float smem[];

    const int e = blockIdx.z;
    const float* Ae = A + (long)e * strideA;
    const float* Be = B + (long)e * strideB;

    const int bm = blockIdx.y, bn = blockIdx.x;
    const int tid = threadIdx.x;
    const int warp = tid >> 5, lane = tid & 31;
    const int wm = warp >> 1, wn = warp & 1;      // 4 warps M x 2 warps N
    const int gid = lane >> 2, tig = lane & 3;

    const int lrow = tid >> 3;
    const int lcol = (tid & 7) * 4;

    const float* Ag = Ae + (long)(bm * BM + lrow) * K + lcol;
    const float* Bg = Be + (long)(bn * BN + lrow) * K + lcol;

    float acc[2][8][4];
#pragma unroll
    for (int mt = 0; mt < 2; mt++)
#pragma unroll
        for (int nt = 0; nt < 8; nt++)
#pragma unroll
            for (int r = 0; r < 4; r++) acc[mt][nt][r] = 0.f;

    const int KT = K / BK;

    // prologue: stages 0..S-2
#pragma unroll
    for (int s = 0; s < S - 1; s++) {
        float* as = smem + s * STAGE_F;
        float* bs = as + BM * LDSW;
        const long koff = (long)s * BK;
#pragma unroll
        for (int i = 0; i < 4; i++) {
            cp_async16(&as[(lrow + i * 32) * LDSW + lcol], Ag + (long)(i * 32) * K + koff);
            cp_async16(&bs[(lrow + i * 32) * LDSW + lcol], Bg + (long)(i * 32) * K + koff);
        }
        cp_commit();
    }

    for (int kt = 0; kt < KT; ++kt) {
        cp_wait<S - 2>();
        __syncthreads();   // stage kt arrived; all warps done with prior compute

        // prefetch stage kt+S-1 (overlaps with cvt + mma below)
        if (kt + S - 1 < KT) {
            const int sp = (kt + S - 1) % S;
            float* as = smem + sp * STAGE_F;
            float* bs = as + BM * LDSW;
            const long koff = (long)(kt + S - 1) * BK;
#pragma unroll
            for (int i = 0; i < 4; i++) {
                cp_async16(&as[(lrow + i * 32) * LDSW + lcol], Ag + (long)(i * 32) * K + koff);
                cp_async16(&bs[(lrow + i * 32) * LDSW + lcol], Bg + (long)(i * 32) * K + koff);
            }
        }
        cp_commit();

        // in-place tf32 rounding of the freshly arrived stage (vectorized)
        {
            float4* sp4 = (float4*)(smem + (kt % S) * STAGE_F);
#pragma unroll
            for (int i = 0; i < 9; i++) {
                float4 v = sp4[tid + 256 * i];
                v.x = __uint_as_float(f2tf32(v.x));
                v.y = __uint_as_float(f2tf32(v.y));
                v.z = __uint_as_float(f2tf32(v.z));
                v.w = __uint_as_float(f2tf32(v.w));
                sp4[tid + 256 * i] = v;
            }
        }
        __syncthreads();   // rounded stage visible to all warps

        const float* as = smem + (kt % S) * STAGE_F;
        const float* bs = as + BM * LDSW;

#pragma unroll
        for (int k8 = 0; k8 < BK / 8; k8++) {
            const int kc = k8 * 8;
            uint32_t afr[2][4];
            uint32_t bfr[8][2];
#pragma unroll
            for (int mt = 0; mt < 2; mt++) {
                const int r = wm * 32 + mt * 16 + gid;
                afr[mt][0] = __float_as_uint(as[r * LDSW + kc + tig]);
                afr[mt][1] = __float_as_uint(as[(r + 8) * LDSW + kc + tig]);
                afr[mt][2] = __float_as_uint(as[r * LDSW + kc + tig + 4]);
                afr[mt][3] = __float_as_uint(as[(r + 8) * LDSW + kc + tig + 4]);
            }
#pragma unroll
            for (int nt = 0; nt < 8; nt++) {
                const int c = wn * 64 + nt * 8 + gid;
                bfr[nt][0] = __float_as_uint(bs[c * LDSW + kc + tig]);
                bfr[nt][1] = __float_as_uint(bs[c * LDSW + kc + tig + 4]);
            }
#pragma unroll
            for (int mt = 0; mt < 2; mt++)
#pragma unroll
                for (int nt = 0; nt < 8; nt++) mma_tf32(acc[mt][nt], afr[mt], bfr[nt]);
        }
    }

    // epilogue
    const long base = (long)e * strideC;
#pragma unroll
    for (int mt = 0; mt < 2; mt++) {
#pragma unroll
        for (int nt = 0; nt < 8; nt++) {
            const int row0 = bm * BM + wm * 32 + mt * 16 + gid;
            const int col = bn * BN + wn * 64 + nt * 8 + tig * 2;
            const long i0 = base + (long)row0 * N + col;
            const long i1 = base + (long)(row0 + 8) * N + col;
            float2 v01 = make_float2(acc[mt][nt][0], acc[mt][nt][1]);
            float2 v23 = make_float2(acc[mt][nt][2], acc[mt][nt][3]);
            if (MODE == 1) {
                const float2 g0 = *reinterpret_cast<const float2*>(Gpre + i0);
                const float2 g1 = *reinterpret_cast<const float2*>(Gpre + i1);
                v01.x = __uint_as_float(f2tf32(v01.x * g0.x / (1.f + __expf(-g0.x))));
                v01.y = __uint_as_float(f2tf32(v01.y * g0.y / (1.f + __expf(-g0.y))));
                v23.x = __uint_as_float(f2tf32(v23.x * g1.x / (1.f + __expf(-g1.x))));
                v23.y = __uint_as_float(f2tf32(v23.y * g1.y / (1.f + __expf(-g1.y))));
            }
            *reinterpret_cast<float2*>(Cout + i0) = v01;
            *reinterpret_cast<float2*>(Cout + i1) = v23;
        }
    }
}

extern "C" void kernel_launch(void* const* d_in, const int* in_sizes, int n_in,
                              void* d_out, int out_size) {
    const float* x    = (const float*)d_in[0];  // [E, C, H]
    const float* gate = (const float*)d_in[1];  // [E, I, H]
    const float* up   = (const float*)d_in[2];  // [E, I, H]
    const float* down = (const float*)d_in[3];  // [E, H, I]
    float* out = (float*)d_out;                 // [E, C, H]

    float* scratch = nullptr;
    cudaGetSymbolAddress((void**)&scratch, g_scratch);

    cudaFuncSetAttribute(gemm_nt<0>, cudaFuncAttributeMaxDynamicSharedMemorySize, SMEM_BYTES);
    cudaFuncSetAttribute(gemm_nt<1>, cudaFuncAttributeMaxDynamicSharedMemorySize, SMEM_BYTES);
    cudaFuncSetAttribute(gemm_nt<2>, cudaFuncAttributeMaxDynamicSharedMemorySize, SMEM_BYTES);

    dim3 blk(THREADS);

    // 1) gate = X · Gateᵀ  -> scratch [E, C, I]
    gemm_nt<0><<<dim3(I_ / BN, C_ / BM, E_), blk, SMEM_BYTES>>>(
        x, gate, nullptr, scratch, I_, H_,
        (long)C_ * H_, (long)I_ * H_, (long)C_ * I_);

    // 2) inter = tf32(silu(gate) * (X · Upᵀ)) -> scratch (in place)
    gemm_nt<1><<<dim3(I_ / BN, C_ / BM, E_), blk, SMEM_BYTES>>>(
        x, up, scratch, scratch, I_, H_,
        (long)C_ * H_, (long)I_ * H_, (long)C_ * I_);

    // 3) out = inter · Downᵀ  [E, C, H]
    gemm_nt<2><<<dim3(H_ / BN, C_ / BM, E_), blk, SMEM_BYTES>>>(
        scratch, down, nullptr, out, H_, I_,
        (long)C_ * I_, (long)H_ * I_, (long)C_ * H_);
}

// round 5
// speedup vs baseline: 1.1608x; 1.1608x over previous
#include <cuda_runtime.h>
#include <cstdint>
#include <math.h>

#define E_ 8
#define C_ 1024
#define H_ 2048
#define I_ 5632

// inter scratch [E, C, I] fp32 (176 MB)
__device__ float g_scratch[(size_t)E_ * C_ * I_];

constexpr int THREADS = 256;

__device__ __forceinline__ uint32_t f2tf32(float x) {
    uint32_t y;
    asm("cvt.rna.tf32.f32 %0, %1;" : "=r"(y) : "f"(x));
    return y;
}
__device__ __forceinline__ void mma_tf32(float (&c)[4], const uint32_t (&a)[4],
                                         const uint32_t (&b)[2]) {
    asm volatile(
        "mma.sync.aligned.m16n8k8.row.col.f32.tf32.tf32.f32 "
        "{%0,%1,%2,%3}, {%4,%5,%6,%7}, {%8,%9}, {%0,%1,%2,%3};\n"
        : "+f"(c[0]), "+f"(c[1]), "+f"(c[2]), "+f"(c[3])
        : "r"(a[0]), "r"(a[1]), "r"(a[2]), "r"(a[3]), "r"(b[0]), "r"(b[1]));
}
__device__ __forceinline__ void cp_async16(void* smem_ptr, const void* gmem_ptr) {
    uint32_t s = (uint32_t)__cvta_generic_to_shared(smem_ptr);
    asm volatile("cp.async.cg.shared.global [%0], [%1], 16;\n" ::"r"(s), "l"(gmem_ptr));
}
__device__ __forceinline__ void cp_commit() { asm volatile("cp.async.commit_group;\n"); }
template <int N>
__device__ __forceinline__ void cp_wait() {
    asm volatile("cp.async.wait_group %0;\n" ::"n"(N));
}
__device__ __forceinline__ float silu(float x) { return x / (1.f + __expf(-x)); }

// ================= fused gate+up kernel =================
// BM=64 rows of C, BN=128 cols of I. Computes G = X·gateᵀ and U = X·upᵀ for the
// same tile, epilogue writes silu(G)*U to scratch. 2-stage cp.async pipeline.
constexpr int FBM = 64, FBN = 128, FBK = 32, FLW = 36;
constexpr int F_STAGE = (FBM + 2 * FBN) * FLW;           // 11520 floats
constexpr int F_SMEM = 2 * F_STAGE * 4;                  // 92160 B

__global__ void __launch_bounds__(THREADS, 2)
gateup_fused(const float* __restrict__ A, const float* __restrict__ Bg,
             const float* __restrict__ Bu, float* __restrict__ Cout) {
    extern __shared__ float smem[];
    constexpr int K = H_, N = I_;
    const int e = blockIdx.z;
    const float* Ae = A + (size_t)e * C_ * K;
    const float* Bge = Bg + (size_t)e * I_ * K;
    const float* Bue = Bu + (size_t)e * I_ * K;

    const int bm = blockIdx.y, bn = blockIdx.x;
    const int tid = threadIdx.x;
    const int warp = tid >> 5, lane = tid & 31;
    const int wm = warp >> 2, wn = warp & 3;     // 2 warps M x 4 warps N
    const int gid = lane >> 2, tig = lane & 3;

    const int lrow = tid >> 3;          // 0..31
    const int lcol = (tid & 7) * 4;

    const float* Ag = Ae + (size_t)(bm * FBM + lrow) * K + lcol;
    const float* Bgg = Bge + (size_t)(bn * FBN + lrow) * K + lcol;
    const float* Bug = Bue + (size_t)(bn * FBN + lrow) * K + lcol;

    float accg[2][4][4], accu[2][4][4];
#pragma unroll
    for (int mt = 0; mt < 2; mt++)
#pragma unroll
        for (int nt = 0; nt < 4; nt++)
#pragma unroll
            for (int r = 0; r < 4; r++) { accg[mt][nt][r] = 0.f; accu[mt][nt][r] = 0.f; }

    const int KT = K / FBK;

    // prologue
    {
        float* as = smem;
        float* bg = as + FBM * FLW;
        float* bu = bg + FBN * FLW;
#pragma unroll
        for (int i = 0; i < 2; i++)
            cp_async16(&as[(lrow + i * 32) * FLW + lcol], Ag + (size_t)(i * 32) * K);
#pragma unroll
        for (int i = 0; i < 4; i++) {
            cp_async16(&bg[(lrow + i * 32) * FLW + lcol], Bgg + (size_t)(i * 32) * K);
            cp_async16(&bu[(lrow + i * 32) * FLW + lcol], Bug + (size_t)(i * 32) * K);
        }
        cp_commit();
    }

    for (int kt = 0; kt < KT; ++kt) {
        if (kt + 1 < KT) {
            const size_t ko = (size_t)(kt + 1) * FBK;
            float* as = smem + ((kt + 1) & 1) * F_STAGE;
            float* bg = as + FBM * FLW;
            float* bu = bg + FBN * FLW;
#pragma unroll
            for (int i = 0; i < 2; i++)
                cp_async16(&as[(lrow + i * 32) * FLW + lcol], Ag + (size_t)(i * 32) * K + ko);
#pragma unroll
            for (int i = 0; i < 4; i++) {
                cp_async16(&bg[(lrow + i * 32) * FLW + lcol], Bgg + (size_t)(i * 32) * K + ko);
                cp_async16(&bu[(lrow + i * 32) * FLW + lcol], Bug + (size_t)(i * 32) * K + ko);
            }
        }
        cp_commit();
        cp_wait<1>();
        __syncthreads();

        const float* as = smem + (kt & 1) * F_STAGE;
        const float* bg = as + FBM * FLW;
        const float* bu = bg + FBN * FLW;

#pragma unroll
        for (int k8 = 0; k8 < FBK / 8; k8++) {
            const int kc = k8 * 8;
            uint32_t afr[2][4], gfr[4][2], ufr[4][2];
#pragma unroll
            for (int mt = 0; mt < 2; mt++) {
                const int r = wm * 32 + mt * 16 + gid;
                afr[mt][0] = f2tf32(as[r * FLW + kc + tig]);
                afr[mt][1] = f2tf32(as[(r + 8) * FLW + kc + tig]);
                afr[mt][2] = f2tf32(as[r * FLW + kc + tig + 4]);
                afr[mt][3] = f2tf32(as[(r + 8) * FLW + kc + tig + 4]);
            }
#pragma unroll
            for (int nt = 0; nt < 4; nt++) {
                const int c = wn * 32 + nt * 8 + gid;
                gfr[nt][0] = f2tf32(bg[c * FLW + kc + tig]);
                gfr[nt][1] = f2tf32(bg[c * FLW + kc + tig + 4]);
                ufr[nt][0] = f2tf32(bu[c * FLW + kc + tig]);
                ufr[nt][1] = f2tf32(bu[c * FLW + kc + tig + 4]);
            }
#pragma unroll
            for (int mt = 0; mt < 2; mt++)
#pragma unroll
                for (int nt = 0; nt < 4; nt++) {
                    mma_tf32(accg[mt][nt], afr[mt], gfr[nt]);
                    mma_tf32(accu[mt][nt], afr[mt], ufr[nt]);
                }
        }
        __syncthreads();
    }

    // epilogue: silu(G)*U -> scratch
    const size_t base = (size_t)e * C_ * N;
#pragma unroll
    for (int mt = 0; mt < 2; mt++) {
#pragma unroll
        for (int nt = 0; nt < 4; nt++) {
            const int row0 = bm * FBM + wm * 32 + mt * 16 + gid;
            const int col = bn * FBN + wn * 32 + nt * 8 + tig * 2;
            const size_t i0 = base + (size_t)row0 * N + col;
            const size_t i1 = base + (size_t)(row0 + 8) * N + col;
            float2 v0 = make_float2(silu(accg[mt][nt][0]) * accu[mt][nt][0],
                                    silu(accg[mt][nt][1]) * accu[mt][nt][1]);
            float2 v1 = make_float2(silu(accg[mt][nt][2]) * accu[mt][nt][2],
                                    silu(accg[mt][nt][3]) * accu[mt][nt][3]);
            *reinterpret_cast<float2*>(Cout + i0) = v0;
            *reinterpret_cast<float2*>(Cout + i1) = v1;
        }
    }
}

// ================= down GEMM (R0-proven config) =================
constexpr int BM = 128, BN = 128, BK = 32, LDSW = 36;
constexpr int D_STAGE = (BM + BN) * LDSW;       // 9216 floats
constexpr int D_SMEM = 2 * D_STAGE * 4;         // 73728 B

__global__ void __launch_bounds__(THREADS)
down_gemm(const float* __restrict__ A, const float* __restrict__ B,
          float* __restrict__ Cout) {
    extern __shared__ float smem[];
    constexpr int K = I_, N = H_;
    const int e = blockIdx.z;
    const float* Ae = A + (size_t)e * C_ * K;
    const float* Be = B + (size_t)e * H_ * K;

    const int bm = blockIdx.y, bn = blockIdx.x;
    const int tid = threadIdx.x;
    const int warp = tid >> 5, lane = tid & 31;
    const int wm = warp >> 1, wn = warp & 1;
    const int gid = lane >> 2, tig = lane & 3;

    const int lrow = tid >> 3;
    const int lcol = (tid & 7) * 4;

    const float* Ag = Ae + (size_t)(bm * BM + lrow) * K + lcol;
    const float* Bg = Be + (size_t)(bn * BN + lrow) * K + lcol;

    float acc[2][8][4];
#pragma unroll
    for (int mt = 0; mt < 2; mt++)
#pragma unroll
        for (int nt = 0; nt < 8; nt++)
#pragma unroll
            for (int r = 0; r < 4; r++) acc[mt][nt][r] = 0.f;

    const int KT = K / BK;
    {
        float* as = smem;
        float* bs = as + BM * LDSW;
#pragma unroll
        for (int i = 0; i < 4; i++) {
            cp_async16(&as[(lrow + i * 32) * LDSW + lcol], Ag + (size_t)(i * 32) * K);
            cp_async16(&bs[(lrow + i * 32) * LDSW + lcol], Bg + (size_t)(i * 32) * K);
        }
        cp_commit();
    }

    for (int kt = 0; kt < KT; ++kt) {
        if (kt + 1 < KT) {
            const size_t ko = (size_t)(kt + 1) * BK;
            float* as = smem + ((kt + 1) & 1) * D_STAGE;
            float* bs = as + BM * LDSW;
#pragma unroll
            for (int i = 0; i < 4; i++) {
                cp_async16(&as[(lrow + i * 32) * LDSW + lcol], Ag + (size_t)(i * 32) * K + ko);
                cp_async16(&bs[(lrow + i * 32) * LDSW + lcol], Bg + (size_t)(i * 32) * K + ko);
            }
        }
        cp_commit();
        cp_wait<1>();
        __syncthreads();

        const float* as = smem + (kt & 1) * D_STAGE;
        const float* bs = as + BM * LDSW;

#pragma unroll
        for (int k8 = 0; k8 < BK / 8; k8++) {
            const int kc = k8 * 8;
            uint32_t afr[2][4], bfr[8][2];
#pragma unroll
            for (int mt = 0; mt < 2; mt++) {
                const int r = wm * 32 + mt * 16 + gid;
                afr[mt][0] = f2tf32(as[r * LDSW + kc + tig]);
                afr[mt][1] = f2tf32(as[(r + 8) * LDSW + kc + tig]);
                afr[mt][2] = f2tf32(as[r * LDSW + kc + tig + 4]);
                afr[mt][3] = f2tf32(as[(r + 8) * LDSW + kc + tig + 4]);
            }
#pragma unroll
            for (int nt = 0; nt < 8; nt++) {
                const int c = wn * 64 + nt * 8 + gid;
                bfr[nt][0] = f2tf32(bs[c * LDSW + kc + tig]);
                bfr[nt][1] = f2tf32(bs[c * LDSW + kc + tig + 4]);
            }
#pragma unroll
            for (int mt = 0; mt < 2; mt++)
#pragma unroll
                for (int nt = 0; nt < 8; nt++) mma_tf32(acc[mt][nt], afr[mt], bfr[nt]);
        }
        __syncthreads();
    }

    const size_t base = (size_t)e * C_ * N;
#pragma unroll
    for (int mt = 0; mt < 2; mt++) {
#pragma unroll
        for (int nt = 0; nt < 8; nt++) {
            const int row0 = bm * BM + wm * 32 + mt * 16 + gid;
            const int col = bn * BN + wn * 64 + nt * 8 + tig * 2;
            const size_t i0 = base + (size_t)row0 * N + col;
            const size_t i1 = base + (size_t)(row0 + 8) * N + col;
            *reinterpret_cast<float2*>(Cout + i0) = make_float2(acc[mt][nt][0], acc[mt][nt][1]);
            *reinterpret_cast<float2*>(Cout + i1) = make_float2(acc[mt][nt][2], acc[mt][nt][3]);
        }
    }
}

extern "C" void kernel_launch(void* const* d_in, const int* in_sizes, int n_in,
                              void* d_out, int out_size) {
    const float* x    = (const float*)d_in[0];  // [E, C, H]
    const float* gate = (const float*)d_in[1];  // [E, I, H]
    const float* up   = (const float*)d_in[2];  // [E, I, H]
    const float* down = (const float*)d_in[3];  // [E, H, I]
    float* out = (float*)d_out;                 // [E, C, H]

    float* scratch = nullptr;
    cudaGetSymbolAddress((void**)&scratch, g_scratch);

    cudaFuncSetAttribute(gateup_fused, cudaFuncAttributeMaxDynamicSharedMemorySize, F_SMEM);
    cudaFuncSetAttribute(down_gemm, cudaFuncAttributeMaxDynamicSharedMemorySize, D_SMEM);

    // fused: inter = silu(X·gateᵀ) * (X·upᵀ)  -> scratch [E, C, I]
    gateup_fused<<<dim3(I_ / FBN, C_ / FBM, E_), THREADS, F_SMEM>>>(x, gate, up, scratch);
    // down: out = inter · downᵀ  [E, C, H]
    down_gemm<<<dim3(H_ / BN, C_ / BM, E_), THREADS, D_SMEM>>>(scratch, down, out);
}

// round 6
// speedup vs baseline: 1.2736x; 1.0972x over previous
#include <cuda_runtime.h>
#include <cstdint>
#include <math.h>

#define E_ 8
#define C_ 1024
#define H_ 2048
#define I_ 5632

// inter/gate scratch [E, C, I] fp32 (176 MB)
__device__ float g_scratch[(size_t)E_ * C_ * I_];

constexpr int BM = 128, BN = 128, BK = 32;
constexpr int LDSW = 36;                      // padded row stride (floats)
constexpr int STAGE_F = (BM + BN) * LDSW;     // 9216 floats per stage
constexpr int SMEM_BYTES = 2 * STAGE_F * 4;   // 73728 B
constexpr int THREADS = 128;                  // 4 warps, warp tile 64x64

__device__ __forceinline__ uint32_t f2tf32(float x) {
    uint32_t y;
    asm("cvt.rna.tf32.f32 %0, %1;" : "=r"(y) : "f"(x));
    return y;
}
__device__ __forceinline__ void mma_tf32(float (&c)[4], const uint32_t (&a)[4],
                                         const uint32_t (&b)[2]) {
    asm volatile(
        "mma.sync.aligned.m16n8k8.row.col.f32.tf32.tf32.f32 "
        "{%0,%1,%2,%3}, {%4,%5,%6,%7}, {%8,%9}, {%0,%1,%2,%3};\n"
        : "+f"(c[0]), "+f"(c[1]), "+f"(c[2]), "+f"(c[3])
        : "r"(a[0]), "r"(a[1]), "r"(a[2]), "r"(a[3]), "r"(b[0]), "r"(b[1]));
}
__device__ __forceinline__ void cp_async16(void* smem_ptr, const void* gmem_ptr) {
    uint32_t s = (uint32_t)__cvta_generic_to_shared(smem_ptr);
    asm volatile("cp.async.cg.shared.global [%0], [%1], 16;\n" ::"r"(s), "l"(gmem_ptr));
}
__device__ __forceinline__ void cp_commit() { asm volatile("cp.async.commit_group;\n"); }
template <int N>
__device__ __forceinline__ void cp_wait() {
    asm volatile("cp.async.wait_group %0;\n" ::"n"(N));
}

// C[e,m,n] = sum_k A[e,m,k] * B[e,n,k]  (NT)
// MODE 0: store raw accumulator           (gate -> scratch)
// MODE 1: out = silu(Gpre)*acc            (up, fused SwiGLU -> scratch in place)
// MODE 2: store raw accumulator           (down -> d_out)
template <int MODE>
__global__ void __launch_bounds__(THREADS)
gemm_nt(const float* __restrict__ A, const float* __restrict__ B,
        const float* __restrict__ Gpre, float* __restrict__ Cout,
        int N, int K, long strideA, long strideB, long strideC) {
    extern __shared__ float smem[];

    const int e = blockIdx.z;
    const float* Ae = A + (long)e * strideA;
    const float* Be = B + (long)e * strideB;

    const int bm = blockIdx.y, bn = blockIdx.x;
    const int tid = threadIdx.x;
    const int warp = tid >> 5, lane = tid & 31;
    const int wm = warp >> 1, wn = warp & 1;      // 2x2 warps, each 64x64
    const int gid = lane >> 2, tig = lane & 3;

    const int lrow = tid >> 3;          // 0..15
    const int lcol = (tid & 7) * 4;

    const float* Ag = Ae + (long)(bm * BM + lrow) * K + lcol;
    const float* Bg = Be + (long)(bn * BN + lrow) * K + lcol;

    float acc[4][8][4];
#pragma unroll
    for (int mt = 0; mt < 4; mt++)
#pragma unroll
        for (int nt = 0; nt < 8; nt++)
#pragma unroll
            for (int r = 0; r < 4; r++) acc[mt][nt][r] = 0.f;

    const int KT = K / BK;

    // prologue: stage 0 (128 threads, 16 rows/pass -> 8 passes per operand)
    {
        float* as = smem;
        float* bs = as + BM * LDSW;
#pragma unroll
        for (int i = 0; i < 8; i++) {
            cp_async16(&as[(lrow + i * 16) * LDSW + lcol], Ag + (long)(i * 16) * K);
            cp_async16(&bs[(lrow + i * 16) * LDSW + lcol], Bg + (long)(i * 16) * K);
        }
        cp_commit();
    }

    for (int kt = 0; kt < KT; ++kt) {
        if (kt + 1 < KT) {
            const long ko = (long)(kt + 1) * BK;
            float* as = smem + ((kt + 1) & 1) * STAGE_F;
            float* bs = as + BM * LDSW;
#pragma unroll
            for (int i = 0; i < 8; i++) {
                cp_async16(&as[(lrow + i * 16) * LDSW + lcol], Ag + (long)(i * 16) * K + ko);
                cp_async16(&bs[(lrow + i * 16) * LDSW + lcol], Bg + (long)(i * 16) * K + ko);
            }
        }
        cp_commit();
        cp_wait<1>();
        __syncthreads();

        const float* as = smem + (kt & 1) * STAGE_F;
        const float* bs = as + BM * LDSW;

#pragma unroll
        for (int k8 = 0; k8 < BK / 8; k8++) {
            const int kc = k8 * 8;
            uint32_t afr[4][4];
            uint32_t bfr[8][2];
#pragma unroll
            for (int mt = 0; mt < 4; mt++) {
                const int r = wm * 64 + mt * 16 + gid;
                afr[mt][0] = f2tf32(as[r * LDSW + kc + tig]);
                afr[mt][1] = f2tf32(as[(r + 8) * LDSW + kc + tig]);
                afr[mt][2] = f2tf32(as[r * LDSW + kc + tig + 4]);
                afr[mt][3] = f2tf32(as[(r + 8) * LDSW + kc + tig + 4]);
            }
#pragma unroll
            for (int nt = 0; nt < 8; nt++) {
                const int c = wn * 64 + nt * 8 + gid;
                bfr[nt][0] = f2tf32(bs[c * LDSW + kc + tig]);
                bfr[nt][1] = f2tf32(bs[c * LDSW + kc + tig + 4]);
            }
#pragma unroll
            for (int mt = 0; mt < 4; mt++)
#pragma unroll
                for (int nt = 0; nt < 8; nt++) mma_tf32(acc[mt][nt], afr[mt], bfr[nt]);
        }
        __syncthreads();
    }

    // epilogue
    const long base = (long)e * strideC;
#pragma unroll
    for (int mt = 0; mt < 4; mt++) {
#pragma unroll
        for (int nt = 0; nt < 8; nt++) {
            const int row0 = bm * BM + wm * 64 + mt * 16 + gid;
            const int col = bn * BN + wn * 64 + nt * 8 + tig * 2;
            const long i0 = base + (long)row0 * N + col;
            const long i1 = base + (long)(row0 + 8) * N + col;
            float2 v01 = make_float2(acc[mt][nt][0], acc[mt][nt][1]);
            float2 v23 = make_float2(acc[mt][nt][2], acc[mt][nt][3]);
            if (MODE == 1) {
                const float2 g0 = *reinterpret_cast<const float2*>(Gpre + i0);
                const float2 g1 = *reinterpret_cast<const float2*>(Gpre + i1);
                v01.x *= g0.x / (1.f + __expf(-g0.x));
                v01.y *= g0.y / (1.f + __expf(-g0.y));
                v23.x *= g1.x / (1.f + __expf(-g1.x));
                v23.y *= g1.y / (1.f + __expf(-g1.y));
            }
            *reinterpret_cast<float2*>(Cout + i0) = v01;
            *reinterpret_cast<float2*>(Cout + i1) = v23;
        }
    }
}

extern "C" void kernel_launch(void* const* d_in, const int* in_sizes, int n_in,
                              void* d_out, int out_size) {
    const float* x    = (const float*)d_in[0];  // [E, C, H]
    const float* gate = (const float*)d_in[1];  // [E, I, H]
    const float* up   = (const float*)d_in[2];  // [E, I, H]
    const float* down = (const float*)d_in[3];  // [E, H, I]
    float* out = (float*)d_out;                 // [E, C, H]

    float* scratch = nullptr;
    cudaGetSymbolAddress((void**)&scratch, g_scratch);

    cudaFuncSetAttribute(gemm_nt<0>, cudaFuncAttributeMaxDynamicSharedMemorySize, SMEM_BYTES);
    cudaFuncSetAttribute(gemm_nt<1>, cudaFuncAttributeMaxDynamicSharedMemorySize, SMEM_BYTES);
    cudaFuncSetAttribute(gemm_nt<2>, cudaFuncAttributeMaxDynamicSharedMemorySize, SMEM_BYTES);

    dim3 blk(THREADS);

    // 1) gate = X · Gateᵀ  -> scratch [E, C, I]
    gemm_nt<0><<<dim3(I_ / BN, C_ / BM, E_), blk, SMEM_BYTES>>>(
        x, gate, nullptr, scratch, I_, H_,
        (long)C_ * H_, (long)I_ * H_, (long)C_ * I_);

    // 2) inter = silu(gate) * (X · Upᵀ) -> scratch (in place)
    gemm_nt<1><<<dim3(I_ / BN, C_ / BM, E_), blk, SMEM_BYTES>>>(
        x, up, scratch, scratch, I_, H_,
        (long)C_ * H_, (long)I_ * H_, (long)C_ * I_);

    // 3) out = inter · Downᵀ  [E, C, H]
    gemm_nt<2><<<dim3(H_ / BN, C_ / BM, E_), blk, SMEM_BYTES>>>(
        scratch, down, nullptr, out, H_, I_,
        (long)C_ * I_, (long)H_ * I_, (long)C_ * H_);
}